// round 6
// baseline (speedup 1.0000x reference)
#include <cuda_runtime.h>
#include <cuda_bf16.h>

#define TH 256
#define MT 32
#define XAP 360   // XA row pitch (K up to 360)
#define XBP 260   // XB row pitch
#define KTP 12    // W tile k-pitch: 8 k + 4 pad (stride 3 float4 -> conflict-free)

// ---------------- device globals (no allocs allowed) ----------------
__device__ float g_scores[8 * 4096];
__device__ float g_probs[8 * 4096];
__device__ float g_cWt[256 * 360];    // combine W transposed [c][k], k padded to 360
__device__ float g_w1t[256 * 256];
__device__ float g_w2at[256 * 256];
__device__ float g_w2bt[256 * 256];
__device__ float g_vft[8 * 256 * 48]; // vf transposed per batch [b][g][a]

typedef unsigned long long ull;

__device__ __forceinline__ ull pk2(float a, float b) {
    ull r;
    asm("mov.b64 %0, {%1,%2};" : "=l"(r) : "f"(a), "f"(b));
    return r;
}
__device__ __forceinline__ void upk2(ull v, float& a, float& b) {
    asm("mov.b64 {%0,%1}, %2;" : "=f"(a), "=f"(b) : "l"(v));
}
__device__ __forceinline__ ull fma2(ull a, ull b, ull c) {
    ull d;
    asm("fma.rn.f32x2 %0, %1, %2, %3;" : "=l"(d) : "l"(a), "l"(b), "l"(c));
    return d;
}

// ---------------- row-wise instance norm over 256 dims, row-major X ----------------
__device__ __forceinline__ void rownorm_t(float* X, int P, int off, float* red1,
                                          float* red2, float* rowM, float* rowR,
                                          int tid) {
    int r = tid >> 3, part = tid & 7;
    float* base = X + r * P + off + part * 32;
    float s1 = 0.f, s2 = 0.f;
#pragma unroll
    for (int j = 0; j < 8; j++) {
        float4 v = *(float4*)(base + 4 * j);
        s1 += (v.x + v.y) + (v.z + v.w);
        s2 += (v.x * v.x + v.y * v.y) + (v.z * v.z + v.w * v.w);
    }
    red1[tid] = s1;
    red2[tid] = s2;
    __syncthreads();
    if (tid < 32) {
        float a = 0.f, bq = 0.f;
#pragma unroll
        for (int p = 0; p < 8; p++) {
            a += red1[tid * 8 + p];
            bq += red2[tid * 8 + p];
        }
        float m = a * (1.f / 256.f);
        float var = bq * (1.f / 256.f) - m * m;
        rowM[tid] = m;
        rowR[tid] = rsqrtf(var + 1e-5f);
    }
    __syncthreads();
    float m = rowM[r], rs = rowR[r];
#pragma unroll
    for (int j = 0; j < 8; j++) {
        float4 v = *(float4*)(base + 4 * j);
        v.x = (v.x - m) * rs;
        v.y = (v.y - m) * rs;
        v.z = (v.z - m) * rs;
        v.w = (v.w - m) * rs;
        *(float4*)(base + 4 * j) = v;
    }
    __syncthreads();
}

// ---------------- GEMM, K-pair packed f32x2 ----------------
// src row-major [32][srcP], dst row-major [32][dstP]+dstOff.
// Wt global transposed [256 c][4*KP4 k]. 8-k double-buffered smem tiles.
// acc[i][c] packs (even-k, odd-k) partial sums; epilogue adds halves.
// act: 0 relu+bias, 1 leaky+bias, 2 scale by invs[row]
__device__ __forceinline__ void gemm_t(const float* __restrict__ src, int srcP,
                                       float* __restrict__ dst, int dstP, int dstOff,
                                       const float* __restrict__ Wt, int KP4,
                                       const float* __restrict__ bias,
                                       const float* __restrict__ invs,
                                       float* W0, float* W1, int Ktiles, int act,
                                       int tid) {
    int tr = tid >> 6;  // 0..3 -> rows 8*tr..8*tr+7
    int tc = tid & 63;  // cols tc + 64c
    ull acc[8][4];
#pragma unroll
    for (int i = 0; i < 8; i++)
#pragma unroll
        for (int c = 0; c < 4; c++) acc[i][c] = 0ull;

    const float4* Wt4 = (const float4*)Wt;
    int sc = tid >> 1, sq = tid & 1;
    float4 stg0, stg1;

    // prologue: tile0 -> W0, prefetch tile1 -> regs
    stg0 = Wt4[sc * KP4 + sq];
    stg1 = Wt4[(sc + 128) * KP4 + sq];
    ((float4*)W0)[sc * 3 + sq] = stg0;
    ((float4*)W0)[(sc + 128) * 3 + sq] = stg1;
    if (Ktiles > 1) {
        stg0 = Wt4[sc * KP4 + 2 + sq];
        stg1 = Wt4[(sc + 128) * KP4 + 2 + sq];
    }
    __syncthreads();

    for (int kt = 0; kt < Ktiles; kt++) {
        float* cur = (kt & 1) ? W1 : W0;
        float* nxt = (kt & 1) ? W0 : W1;
        if (kt + 1 < Ktiles) {
            ((float4*)nxt)[sc * 3 + sq] = stg0;
            ((float4*)nxt)[(sc + 128) * 3 + sq] = stg1;
            if (kt + 2 < Ktiles) {
                stg0 = Wt4[sc * KP4 + (kt + 2) * 2 + sq];
                stg1 = Wt4[(sc + 128) * KP4 + (kt + 2) * 2 + sq];
            }
        }
        const float* xb = src + (8 * tr) * srcP + kt * 8;
#pragma unroll
        for (int kg = 0; kg < 2; kg++) {
            ull xp01[8], xp23[8];
#pragma unroll
            for (int i = 0; i < 8; i++) {
                float4 q = *(const float4*)(xb + i * srcP + kg * 4);  // warp-uniform
                xp01[i] = pk2(q.x, q.y);
                xp23[i] = pk2(q.z, q.w);
            }
#pragma unroll
            for (int c = 0; c < 4; c++) {
                float4 w = *(const float4*)(cur + (tc + 64 * c) * KTP + kg * 4);
                ull w01 = pk2(w.x, w.y);
                ull w23 = pk2(w.z, w.w);
#pragma unroll
                for (int i = 0; i < 8; i++) {
                    acc[i][c] = fma2(xp01[i], w01, acc[i][c]);
                    acc[i][c] = fma2(xp23[i], w23, acc[i][c]);
                }
            }
        }
        __syncthreads();
    }

    // epilogue
#pragma unroll
    for (int c = 0; c < 4; c++) {
        int col = tc + 64 * c;
        float bb = (act != 2) ? __ldg(bias + col) : 0.f;
#pragma unroll
        for (int i = 0; i < 8; i++) {
            float lo, hi;
            upk2(acc[i][c], lo, hi);
            float y = lo + hi;
            if (act == 2) {
                y *= invs[8 * tr + i];
            } else {
                y += bb;
                y = (act == 0) ? fmaxf(y, 0.f) : ((y > 0.f) ? y : 0.01f * y);
            }
            dst[(8 * tr + i) * dstP + dstOff + col] = y;
        }
    }
    __syncthreads();
}

// ---------------- prep: transpose weights / vf into device globals ----------------
__global__ void prep_kernel(const float* __restrict__ cW, const float* __restrict__ w1,
                            const float* __restrict__ w2a, const float* __restrict__ w2b,
                            const float* __restrict__ vf) {
    int i = blockIdx.x * 256 + threadIdx.x;
    if (i < 92160) {
        int c = i / 360, k = i - 360 * c;
        g_cWt[i] = (k < 356) ? cW[k * 256 + c] : 0.f;
        return;
    }
    i -= 92160;
    if (i < 65536) { g_w1t[i] = w1[((i & 255) << 8) + (i >> 8)]; return; }
    i -= 65536;
    if (i < 65536) { g_w2at[i] = w2a[((i & 255) << 8) + (i >> 8)]; return; }
    i -= 65536;
    if (i < 65536) { g_w2bt[i] = w2b[((i & 255) << 8) + (i >> 8)]; return; }
    i -= 65536;
    if (i < 98304) {
        int b = i / 12288, r = i - b * 12288;
        int g = r / 48, a = r - 48 * g;
        g_vft[i] = vf[b * 12288 + a * 256 + g];
    }
}

// ---------------- main fused kernel: one CTA = 32 subset rows of one batch ----------------
__global__ void __launch_bounds__(TH, 2)
fused_main(const float* __restrict__ vmask, const float* __restrict__ eoh_g,
           const int* __restrict__ subs, const float* __restrict__ cB,
           const float* __restrict__ b1, const float* __restrict__ b2a,
           const float* __restrict__ b2b, const float* __restrict__ sW,
           const float* __restrict__ sB) {
    extern __shared__ float sm[];
    float* XA = sm;                   // 32*360 = 11520
    float* XB = sm + 11520;           // 32*260 = 8320
    float* W0 = sm + 19840;           // 256*12 = 3072
    float* W1 = sm + 22912;           // 3072
    float* red1 = sm + 25984;         // 256
    float* red2 = sm + 26240;         // 256
    float* rowM = sm + 26496;         // 32
    float* rowR = sm + 26528;         // 32
    float* invs = sm + 26560;         // 32
    float* maskv = sm + 26592;        // 48
    float* msq = sm + 26640;          // 48
    float* eoh = sm + 26688;          // 240 -> total 26928 floats

    int tid = threadIdx.x;
    int b = blockIdx.x >> 7;            // 128 tiles per batch
    int s0 = (blockIdx.x & 127) * MT;

    float* SRAW = W0;  // raw subset tile [32*48] packed (1536 <= 3072)
    float* SX = XB;    // masked X for stage A, row-major pitch 48 (1536 <= 8320)

    // ---- loads ----
    if (tid < 48) {
        float m = vmask[b * 48 + tid];
        maskv[tid] = m;
        msq[tid] = m * m;
    }
    if (tid < 240) eoh[tid] = eoh_g[b * 240 + tid];
    {
        const int* sb = subs + (b * 4096 + s0) * 48;
        for (int idx = tid; idx < 1536; idx += TH) SRAW[idx] = (float)sb[idx];
    }
    __syncthreads();

    // ---- counts (160 thr) + subset size (32 thr) ----
    if (tid < 160) {
        int r = tid / 5, e = tid - 5 * (tid / 5);
        float c = 0.f;
        for (int a = 0; a < 48; a++) c += SRAW[r * 48 + a] * eoh[a * 5 + e];
        red2[tid] = c;
    } else if (tid < 192) {
        int r = tid - 160;
        float sz = 0.f;
        for (int a = 0; a < 48; a++) sz += SRAW[r * 48 + a] * maskv[a];
        invs[r] = 1.f / (sz + 1e-4f);
    }
    __syncthreads();

    // ---- thermometer rows + K-pad + SX = s*m^2 ----
    if (tid < 32) {
        int r = tid;
        float cnt[5];
#pragma unroll
        for (int e = 0; e < 5; e++) cnt[e] = red2[r * 5 + e];
        float* xr = XA + r * XAP;
#pragma unroll
        for (int e = 0; e < 5; e++)
            for (int j = 0; j < 20; j++)
                xr[e * 20 + j] = ((float)j < cnt[e]) ? 1.f : 0.f;
        xr[356] = 0.f; xr[357] = 0.f; xr[358] = 0.f; xr[359] = 0.f;
    }
    for (int idx = tid; idx < 1536; idx += TH) {
        int a = idx - 48 * (idx / 48);
        SX[idx] = SRAW[idx] * msq[a];
    }
    __syncthreads();

    // ---- stage A: meanfeat = (SX @ vf_t) * invs -> XA cols 100..355 ----
    gemm_t(SX, 48, XA, XAP, 100, g_vft + b * 12288, 12, 0, invs, W0, W1, 6, 2, tid);

    rownorm_t(XA, XAP, 100, red1, red2, rowM, rowR, tid);            // subset_weighted_norm
    gemm_t(XA, XAP, XB, XBP, 0, g_cWt, 90, cB, 0, W0, W1, 45, 0, tid);   // combine + relu
    rownorm_t(XB, XBP, 0, red1, red2, rowM, rowR, tid);              // norm_post_combine
    gemm_t(XB, XBP, XA, XAP, 0, g_w1t, 64, b1, 0, W0, W1, 32, 0, tid);   // l1 + relu
    gemm_t(XA, XAP, XB, XBP, 0, g_w2at, 64, b2a, 0, W0, W1, 32, 1, tid); // l2a + leaky
    gemm_t(XB, XBP, XA, XAP, 0, g_w2bt, 64, b2b, 0, W0, W1, 32, 0, tid); // l2b: leaky+relu==relu
    rownorm_t(XA, XAP, 0, red1, red2, rowM, rowR, tid);              // norm_pre_score

    // ---- score head ----
    {
        int r = tid >> 3, part = tid & 7;
        const float* xr = XA + r * XAP + part * 32;
        float s = 0.f;
#pragma unroll
        for (int j = 0; j < 8; j++) {
            float4 x = *(const float4*)(xr + 4 * j);
            float4 w = __ldg((const float4*)(sW + part * 32 + 4 * j));
            s += x.x * w.x + x.y * w.y + x.z * w.z + x.w * w.w;
        }
        red1[tid] = s;
        __syncthreads();
        if (tid < 32) {
            float t = 0.f;
#pragma unroll
            for (int p = 0; p < 8; p++) t += red1[tid * 8 + p];
            g_scores[b * 4096 + s0 + tid] = t + __ldg(sB);
        }
    }
}

// ---------------- per-batch softmax over 4096 scores ----------------
__global__ void softmax_kernel(float* __restrict__ probs_out) {
    __shared__ float sbuf[32];
    __shared__ float sval;
    int b = blockIdx.x, t = threadIdx.x, lane = t & 31, wid = t >> 5;
    const float* sc = g_scores + b * 4096;
    float v0 = sc[t], v1 = sc[t + 1024], v2 = sc[t + 2048], v3 = sc[t + 3072];
    float mx = fmaxf(fmaxf(v0, v1), fmaxf(v2, v3));
#pragma unroll
    for (int o = 16; o; o >>= 1) mx = fmaxf(mx, __shfl_xor_sync(0xffffffffu, mx, o));
    if (lane == 0) sbuf[wid] = mx;
    __syncthreads();
    if (t < 32) {
        float m = sbuf[t];
#pragma unroll
        for (int o = 16; o; o >>= 1) m = fmaxf(m, __shfl_xor_sync(0xffffffffu, m, o));
        if (t == 0) sval = m;
    }
    __syncthreads();
    mx = sval;
    float e0 = expf(v0 - mx), e1 = expf(v1 - mx), e2 = expf(v2 - mx), e3 = expf(v3 - mx);
    float sum = e0 + e1 + e2 + e3;
#pragma unroll
    for (int o = 16; o; o >>= 1) sum += __shfl_xor_sync(0xffffffffu, sum, o);
    __syncthreads();
    if (lane == 0) sbuf[wid] = sum;
    __syncthreads();
    if (t < 32) {
        float s = sbuf[t];
#pragma unroll
        for (int o = 16; o; o >>= 1) s += __shfl_xor_sync(0xffffffffu, s, o);
        if (t == 0) sval = s;
    }
    __syncthreads();
    float inv = 1.f / sval;
    float p0 = e0 * inv, p1 = e1 * inv, p2 = e2 * inv, p3 = e3 * inv;
    probs_out[b * 4096 + t] = p0;
    probs_out[b * 4096 + t + 1024] = p1;
    probs_out[b * 4096 + t + 2048] = p2;
    probs_out[b * 4096 + t + 3072] = p3;
    g_probs[b * 4096 + t] = p0;
    g_probs[b * 4096 + t + 1024] = p1;
    g_probs[b * 4096 + t + 2048] = p2;
    g_probs[b * 4096 + t + 3072] = p3;
}

// ---------------- zero + scatter into spectral bins ----------------
__global__ void zero_kernel(float* __restrict__ p, int n) {
    int idx = blockIdx.x * blockDim.x + threadIdx.x;
    if (idx < n) p[idx] = 0.f;
}

__global__ void scatter_kernel(const int* __restrict__ midx,
                               const float* __restrict__ inten,
                               float* __restrict__ spect) {
    int idx = blockIdx.x * blockDim.x + threadIdx.x;
    if (idx >= 8 * 4096 * 32) return;
    int b = idx >> 17;
    int s = (idx >> 5) & 4095;
    float w = inten[idx] * g_probs[b * 4096 + s];
    atomicAdd(spect + b * 65536 + midx[idx], w);
}

// ---------------- launch ----------------
extern "C" void kernel_launch(void* const* d_in, const int* in_sizes, int n_in,
                              void* d_out, int out_size) {
    const float* vf    = (const float*)d_in[0];
    const float* vmask = (const float*)d_in[1];
    const float* eoh   = (const float*)d_in[2];
    const int*   subs  = (const int*)d_in[4];
    const int*   midx  = (const int*)d_in[6];
    const float* inten = (const float*)d_in[7];
    const float* cW    = (const float*)d_in[8];
    const float* cB    = (const float*)d_in[9];
    const float* w1    = (const float*)d_in[10];
    const float* b1    = (const float*)d_in[11];
    const float* w2a   = (const float*)d_in[12];
    const float* b2a   = (const float*)d_in[13];
    const float* w2b   = (const float*)d_in[14];
    const float* b2b   = (const float*)d_in[15];
    const float* sW    = (const float*)d_in[16];
    const float* sB    = (const float*)d_in[17];
    float* out = (float*)d_out;

    int pOff = out_size - 8 * 4096;  // spect first, probs second
    size_t smem = (size_t)26928 * sizeof(float);
    cudaFuncSetAttribute(fused_main, cudaFuncAttributeMaxDynamicSharedMemorySize,
                         (int)smem);

    prep_kernel<<<1512, 256>>>(cW, w1, w2a, w2b, vf);
    zero_kernel<<<(pOff + 511) / 512, 512>>>(out, pOff);
    fused_main<<<1024, TH, smem>>>(vmask, eoh, subs, cB, b1, b2a, b2b, sW, sB);
    softmax_kernel<<<8, 1024>>>(out + pOff);
    scatter_kernel<<<2048, 512>>>(midx, inten, out);
}

// round 8
// speedup vs baseline: 1.0009x; 1.0009x over previous
#include <cuda_runtime.h>
#include <cuda_bf16.h>

#define TH 256
#define MT 32
#define XAP 360   // XA row pitch (K up to 360)
#define XBP 260   // XB row pitch
#define KTP 12    // W tile k-pitch: 8 k + 4 pad (stride 3 float4 -> conflict-free)

// ---------------- device globals (no allocs allowed) ----------------
__device__ float g_scores[8 * 4096];
__device__ float g_probs[8 * 4096];
__device__ float g_cWt[256 * 360];    // combine W transposed [c][k], k padded to 360
__device__ float g_w1t[256 * 256];
__device__ float g_w2at[256 * 256];
__device__ float g_w2bt[256 * 256];
__device__ float g_vft[8 * 256 * 48]; // vf transposed per batch [b][g][a]

typedef unsigned long long ull;

__device__ __forceinline__ ull pk2(float a, float b) {
    ull r;
    asm("mov.b64 %0, {%1,%2};" : "=l"(r) : "f"(a), "f"(b));
    return r;
}
__device__ __forceinline__ void upk2(ull v, float& a, float& b) {
    asm("mov.b64 {%0,%1}, %2;" : "=f"(a), "=f"(b) : "l"(v));
}
__device__ __forceinline__ ull fma2(ull a, ull b, ull c) {
    ull d;
    asm("fma.rn.f32x2 %0, %1, %2, %3;" : "=l"(d) : "l"(a), "l"(b), "l"(c));
    return d;
}

// ---------------- row-wise instance norm over 256 dims, row-major X ----------------
__device__ __forceinline__ void rownorm_t(float* X, int P, int off, float* red1,
                                          float* red2, float* rowM, float* rowR,
                                          int tid) {
    int r = tid >> 3, part = tid & 7;
    float* base = X + r * P + off + part * 32;
    float s1 = 0.f, s2 = 0.f;
#pragma unroll
    for (int j = 0; j < 8; j++) {
        float4 v = *(float4*)(base + 4 * j);
        s1 += (v.x + v.y) + (v.z + v.w);
        s2 += (v.x * v.x + v.y * v.y) + (v.z * v.z + v.w * v.w);
    }
    red1[tid] = s1;
    red2[tid] = s2;
    __syncthreads();
    if (tid < 32) {
        float a = 0.f, bq = 0.f;
#pragma unroll
        for (int p = 0; p < 8; p++) {
            a += red1[tid * 8 + p];
            bq += red2[tid * 8 + p];
        }
        float m = a * (1.f / 256.f);
        float var = bq * (1.f / 256.f) - m * m;
        rowM[tid] = m;
        rowR[tid] = rsqrtf(var + 1e-5f);
    }
    __syncthreads();
    float m = rowM[r], rs = rowR[r];
#pragma unroll
    for (int j = 0; j < 8; j++) {
        float4 v = *(float4*)(base + 4 * j);
        v.x = (v.x - m) * rs;
        v.y = (v.y - m) * rs;
        v.z = (v.z - m) * rs;
        v.w = (v.w - m) * rs;
        *(float4*)(base + 4 * j) = v;
    }
    __syncthreads();
}

// ---------------- GEMM, K-pair packed f32x2 ----------------
// src row-major [32][srcP], dst row-major [32][dstP]+dstOff.
// Wt global transposed [256 c][4*KP4 k]. 8-k double-buffered smem tiles.
// acc[i][c] packs (even-k, odd-k) partial sums; epilogue adds halves.
// act: 0 relu+bias, 1 leaky+bias, 2 scale by invs[row]
__device__ __forceinline__ void gemm_t(const float* __restrict__ src, int srcP,
                                       float* __restrict__ dst, int dstP, int dstOff,
                                       const float* __restrict__ Wt, int KP4,
                                       const float* __restrict__ bias,
                                       const float* __restrict__ invs,
                                       float* W0, float* W1, int Ktiles, int act,
                                       int tid) {
    int tr = tid >> 6;  // 0..3 -> rows 8*tr..8*tr+7
    int tc = tid & 63;  // cols tc + 64c
    ull acc[8][4];
#pragma unroll
    for (int i = 0; i < 8; i++)
#pragma unroll
        for (int c = 0; c < 4; c++) acc[i][c] = 0ull;

    const float4* Wt4 = (const float4*)Wt;
    int sc = tid >> 1, sq = tid & 1;
    float4 stg0, stg1;

    // prologue: tile0 -> W0, prefetch tile1 -> regs
    stg0 = Wt4[sc * KP4 + sq];
    stg1 = Wt4[(sc + 128) * KP4 + sq];
    ((float4*)W0)[sc * 3 + sq] = stg0;
    ((float4*)W0)[(sc + 128) * 3 + sq] = stg1;
    if (Ktiles > 1) {
        stg0 = Wt4[sc * KP4 + 2 + sq];
        stg1 = Wt4[(sc + 128) * KP4 + 2 + sq];
    }
    __syncthreads();

    for (int kt = 0; kt < Ktiles; kt++) {
        float* cur = (kt & 1) ? W1 : W0;
        float* nxt = (kt & 1) ? W0 : W1;
        if (kt + 1 < Ktiles) {
            ((float4*)nxt)[sc * 3 + sq] = stg0;
            ((float4*)nxt)[(sc + 128) * 3 + sq] = stg1;
            if (kt + 2 < Ktiles) {
                stg0 = Wt4[sc * KP4 + (kt + 2) * 2 + sq];
                stg1 = Wt4[(sc + 128) * KP4 + (kt + 2) * 2 + sq];
            }
        }
        const float* xb = src + (8 * tr) * srcP + kt * 8;
#pragma unroll
        for (int kg = 0; kg < 2; kg++) {
            ull xp01[8], xp23[8];
#pragma unroll
            for (int i = 0; i < 8; i++) {
                float4 q = *(const float4*)(xb + i * srcP + kg * 4);  // warp-uniform
                xp01[i] = pk2(q.x, q.y);
                xp23[i] = pk2(q.z, q.w);
            }
#pragma unroll
            for (int c = 0; c < 4; c++) {
                float4 w = *(const float4*)(cur + (tc + 64 * c) * KTP + kg * 4);
                ull w01 = pk2(w.x, w.y);
                ull w23 = pk2(w.z, w.w);
#pragma unroll
                for (int i = 0; i < 8; i++) {
                    acc[i][c] = fma2(xp01[i], w01, acc[i][c]);
                    acc[i][c] = fma2(xp23[i], w23, acc[i][c]);
                }
            }
        }
        __syncthreads();
    }

    // epilogue
#pragma unroll
    for (int c = 0; c < 4; c++) {
        int col = tc + 64 * c;
        float bb = (act != 2) ? __ldg(bias + col) : 0.f;
#pragma unroll
        for (int i = 0; i < 8; i++) {
            float lo, hi;
            upk2(acc[i][c], lo, hi);
            float y = lo + hi;
            if (act == 2) {
                y *= invs[8 * tr + i];
            } else {
                y += bb;
                y = (act == 0) ? fmaxf(y, 0.f) : ((y > 0.f) ? y : 0.01f * y);
            }
            dst[(8 * tr + i) * dstP + dstOff + col] = y;
        }
    }
    __syncthreads();
}

// ---------------- prep: transpose weights / vf into device globals ----------------
__global__ void prep_kernel(const float* __restrict__ cW, const float* __restrict__ w1,
                            const float* __restrict__ w2a, const float* __restrict__ w2b,
                            const float* __restrict__ vf) {
    int i = blockIdx.x * 256 + threadIdx.x;
    if (i < 92160) {
        int c = i / 360, k = i - 360 * c;
        g_cWt[i] = (k < 356) ? cW[k * 256 + c] : 0.f;
        return;
    }
    i -= 92160;
    if (i < 65536) { g_w1t[i] = w1[((i & 255) << 8) + (i >> 8)]; return; }
    i -= 65536;
    if (i < 65536) { g_w2at[i] = w2a[((i & 255) << 8) + (i >> 8)]; return; }
    i -= 65536;
    if (i < 65536) { g_w2bt[i] = w2b[((i & 255) << 8) + (i >> 8)]; return; }
    i -= 65536;
    if (i < 98304) {
        int b = i / 12288, r = i - b * 12288;
        int g = r / 48, a = r - 48 * g;
        g_vft[i] = vf[b * 12288 + a * 256 + g];
    }
}

// ---------------- main fused kernel: one CTA = 32 subset rows of one batch ----------------
__global__ void __launch_bounds__(TH, 2)
fused_main(const float* __restrict__ vmask, const float* __restrict__ eoh_g,
           const int* __restrict__ subs, const float* __restrict__ cB,
           const float* __restrict__ b1, const float* __restrict__ b2a,
           const float* __restrict__ b2b, const float* __restrict__ sW,
           const float* __restrict__ sB) {
    extern __shared__ float sm[];
    float* XA = sm;                   // 32*360 = 11520
    float* XB = sm + 11520;           // 32*260 = 8320
    float* W0 = sm + 19840;           // 256*12 = 3072
    float* W1 = sm + 22912;           // 3072
    float* red1 = sm + 25984;         // 256
    float* red2 = sm + 26240;         // 256
    float* rowM = sm + 26496;         // 32
    float* rowR = sm + 26528;         // 32
    float* invs = sm + 26560;         // 32
    float* maskv = sm + 26592;        // 48
    float* msq = sm + 26640;          // 48
    float* eoh = sm + 26688;          // 240 -> total 26928 floats

    int tid = threadIdx.x;
    int b = blockIdx.x >> 7;            // 128 tiles per batch
    int s0 = (blockIdx.x & 127) * MT;

    float* SRAW = W0;  // raw subset tile [32*48] packed (1536 <= 3072)
    float* SX = XB;    // masked X for stage A, row-major pitch 48 (1536 <= 8320)

    // ---- loads ----
    if (tid < 48) {
        float m = vmask[b * 48 + tid];
        maskv[tid] = m;
        msq[tid] = m * m;
    }
    if (tid < 240) eoh[tid] = eoh_g[b * 240 + tid];
    {
        const int* sb = subs + (b * 4096 + s0) * 48;
        for (int idx = tid; idx < 1536; idx += TH) SRAW[idx] = (float)sb[idx];
    }
    __syncthreads();

    // ---- counts (160 thr) + subset size (32 thr) ----
    if (tid < 160) {
        int r = tid / 5, e = tid - 5 * (tid / 5);
        float c = 0.f;
        for (int a = 0; a < 48; a++) c += SRAW[r * 48 + a] * eoh[a * 5 + e];
        red2[tid] = c;
    } else if (tid < 192) {
        int r = tid - 160;
        float sz = 0.f;
        for (int a = 0; a < 48; a++) sz += SRAW[r * 48 + a] * maskv[a];
        invs[r] = 1.f / (sz + 1e-4f);
    }
    __syncthreads();

    // ---- thermometer rows + K-pad + SX = s*m^2 ----
    if (tid < 32) {
        int r = tid;
        float cnt[5];
#pragma unroll
        for (int e = 0; e < 5; e++) cnt[e] = red2[r * 5 + e];
        float* xr = XA + r * XAP;
#pragma unroll
        for (int e = 0; e < 5; e++)
            for (int j = 0; j < 20; j++)
                xr[e * 20 + j] = ((float)j < cnt[e]) ? 1.f : 0.f;
        xr[356] = 0.f; xr[357] = 0.f; xr[358] = 0.f; xr[359] = 0.f;
    }
    for (int idx = tid; idx < 1536; idx += TH) {
        int a = idx - 48 * (idx / 48);
        SX[idx] = SRAW[idx] * msq[a];
    }
    __syncthreads();

    // ---- stage A: meanfeat = (SX @ vf_t) * invs -> XA cols 100..355 ----
    gemm_t(SX, 48, XA, XAP, 100, g_vft + b * 12288, 12, 0, invs, W0, W1, 6, 2, tid);

    rownorm_t(XA, XAP, 100, red1, red2, rowM, rowR, tid);            // subset_weighted_norm
    gemm_t(XA, XAP, XB, XBP, 0, g_cWt, 90, cB, 0, W0, W1, 45, 0, tid);   // combine + relu
    rownorm_t(XB, XBP, 0, red1, red2, rowM, rowR, tid);              // norm_post_combine
    gemm_t(XB, XBP, XA, XAP, 0, g_w1t, 64, b1, 0, W0, W1, 32, 0, tid);   // l1 + relu
    gemm_t(XA, XAP, XB, XBP, 0, g_w2at, 64, b2a, 0, W0, W1, 32, 1, tid); // l2a + leaky
    gemm_t(XB, XBP, XA, XAP, 0, g_w2bt, 64, b2b, 0, W0, W1, 32, 0, tid); // l2b: leaky+relu==relu
    rownorm_t(XA, XAP, 0, red1, red2, rowM, rowR, tid);              // norm_pre_score

    // ---- score head ----
    {
        int r = tid >> 3, part = tid & 7;
        const float* xr = XA + r * XAP + part * 32;
        float s = 0.f;
#pragma unroll
        for (int j = 0; j < 8; j++) {
            float4 x = *(const float4*)(xr + 4 * j);
            float4 w = __ldg((const float4*)(sW + part * 32 + 4 * j));
            s += x.x * w.x + x.y * w.y + x.z * w.z + x.w * w.w;
        }
        red1[tid] = s;
        __syncthreads();
        if (tid < 32) {
            float t = 0.f;
#pragma unroll
            for (int p = 0; p < 8; p++) t += red1[tid * 8 + p];
            g_scores[b * 4096 + s0 + tid] = t + __ldg(sB);
        }
    }
}

// ---------------- per-batch softmax over 4096 scores ----------------
__global__ void softmax_kernel(float* __restrict__ probs_out) {
    __shared__ float sbuf[32];
    __shared__ float sval;
    int b = blockIdx.x, t = threadIdx.x, lane = t & 31, wid = t >> 5;
    const float* sc = g_scores + b * 4096;
    float v0 = sc[t], v1 = sc[t + 1024], v2 = sc[t + 2048], v3 = sc[t + 3072];
    float mx = fmaxf(fmaxf(v0, v1), fmaxf(v2, v3));
#pragma unroll
    for (int o = 16; o; o >>= 1) mx = fmaxf(mx, __shfl_xor_sync(0xffffffffu, mx, o));
    if (lane == 0) sbuf[wid] = mx;
    __syncthreads();
    if (t < 32) {
        float m = sbuf[t];
#pragma unroll
        for (int o = 16; o; o >>= 1) m = fmaxf(m, __shfl_xor_sync(0xffffffffu, m, o));
        if (t == 0) sval = m;
    }
    __syncthreads();
    mx = sval;
    float e0 = expf(v0 - mx), e1 = expf(v1 - mx), e2 = expf(v2 - mx), e3 = expf(v3 - mx);
    float sum = e0 + e1 + e2 + e3;
#pragma unroll
    for (int o = 16; o; o >>= 1) sum += __shfl_xor_sync(0xffffffffu, sum, o);
    __syncthreads();
    if (lane == 0) sbuf[wid] = sum;
    __syncthreads();
    if (t < 32) {
        float s = sbuf[t];
#pragma unroll
        for (int o = 16; o; o >>= 1) s += __shfl_xor_sync(0xffffffffu, s, o);
        if (t == 0) sval = s;
    }
    __syncthreads();
    float inv = 1.f / sval;
    float p0 = e0 * inv, p1 = e1 * inv, p2 = e2 * inv, p3 = e3 * inv;
    probs_out[b * 4096 + t] = p0;
    probs_out[b * 4096 + t + 1024] = p1;
    probs_out[b * 4096 + t + 2048] = p2;
    probs_out[b * 4096 + t + 3072] = p3;
    g_probs[b * 4096 + t] = p0;
    g_probs[b * 4096 + t + 1024] = p1;
    g_probs[b * 4096 + t + 2048] = p2;
    g_probs[b * 4096 + t + 3072] = p3;
}

// ---------------- zero + scatter into spectral bins ----------------
__global__ void zero_kernel(float* __restrict__ p, int n) {
    int idx = blockIdx.x * blockDim.x + threadIdx.x;
    if (idx < n) p[idx] = 0.f;
}

__global__ void scatter_kernel(const int* __restrict__ midx,
                               const float* __restrict__ inten,
                               float* __restrict__ spect) {
    int idx = blockIdx.x * blockDim.x + threadIdx.x;
    if (idx >= 8 * 4096 * 32) return;
    int b = idx >> 17;
    int s = (idx >> 5) & 4095;
    float w = inten[idx] * g_probs[b * 4096 + s];
    atomicAdd(spect + b * 65536 + midx[idx], w);
}

// ---------------- launch ----------------
extern "C" void kernel_launch(void* const* d_in, const int* in_sizes, int n_in,
                              void* d_out, int out_size) {
    const float* vf    = (const float*)d_in[0];
    const float* vmask = (const float*)d_in[1];
    const float* eoh   = (const float*)d_in[2];
    const int*   subs  = (const int*)d_in[4];
    const int*   midx  = (const int*)d_in[6];
    const float* inten = (const float*)d_in[7];
    const float* cW    = (const float*)d_in[8];
    const float* cB    = (const float*)d_in[9];
    const float* w1    = (const float*)d_in[10];
    const float* b1    = (const float*)d_in[11];
    const float* w2a   = (const float*)d_in[12];
    const float* b2a   = (const float*)d_in[13];
    const float* w2b   = (const float*)d_in[14];
    const float* b2b   = (const float*)d_in[15];
    const float* sW    = (const float*)d_in[16];
    const float* sB    = (const float*)d_in[17];
    float* out = (float*)d_out;

    int pOff = out_size - 8 * 4096;  // spect first, probs second
    size_t smem = (size_t)26928 * sizeof(float);
    cudaFuncSetAttribute(fused_main, cudaFuncAttributeMaxDynamicSharedMemorySize,
                         (int)smem);

    prep_kernel<<<1512, 256>>>(cW, w1, w2a, w2b, vf);
    zero_kernel<<<(pOff + 511) / 512, 512>>>(out, pOff);
    fused_main<<<1024, TH, smem>>>(vmask, eoh, subs, cB, b1, b2a, b2b, sW, sB);
    softmax_kernel<<<8, 1024>>>(out + pOff);
    scatter_kernel<<<2048, 512>>>(midx, inten, out);
}